// round 1
// baseline (speedup 1.0000x reference)
#include <cuda_runtime.h>
#include <math.h>

#define BB 64
#define QQ 4096
#define NN 256
#define NC 20          // foreground classes
#define NL 21          // logits per query (NC + 1)
#define QT 32          // q-tile per block

#define COST_CLASS  1.0f
#define COST_CENTER 5.0f
#define COST_IOU    2.0f
#define CT2         4.0f        // CENTER_THRESHOLD^2
#define INF_REPLACE 1000000.0f

__global__ __launch_bounds__(256) void matcher_kernel(
    const float* __restrict__ logits,    // [B, Q, 21]
    const float* __restrict__ pboxes,    // [B, Q, 6]
    const int*   __restrict__ labels,    // [B, N]
    const float* __restrict__ tboxes,    // [B, N, 6]
    float*       __restrict__ out)       // [B, Q, N]
{
    const int blocks_per_b = QQ / QT;
    const int b  = blockIdx.x / blocks_per_b;
    const int q0 = (blockIdx.x % blocks_per_b) * QT;
    const int t  = threadIdx.x;           // t == target index n (0..255)

    __shared__ float s_logits[QT * NL];   // staged logits tile
    __shared__ float s_probs[QT * NC];    // softmax fg probs per q
    __shared__ float s_pc[QT][3];         // pred centers
    __shared__ float s_ps[QT][3];         // pred sizes

    // ---- per-thread target data (held in registers for the whole block) ----
    const float* tb = tboxes + ((size_t)b * NN + t) * 6;
    const float tcx = tb[0], tcy = tb[1], tcz = tb[2];
    const float tsx = tb[3], tsy = tb[4], tsz = tb[5];
    const int   lbl = labels[b * NN + t];
    const float vol2  = tsx * tsy * tsz;
    const float min2x = tcx - 0.5f * tsx, max2x = tcx + 0.5f * tsx;
    const float min2y = tcy - 0.5f * tsy, max2y = tcy + 0.5f * tsy;
    const float min2z = tcz - 0.5f * tsz, max2z = tcz + 0.5f * tsz;

    // ---- cooperative, coalesced stage of logits + pred boxes ----
    {
        const float* lg = logits + ((size_t)b * QQ + q0) * NL;
        for (int i = t; i < QT * NL; i += 256) s_logits[i] = lg[i];

        const float* pb = pboxes + ((size_t)b * QQ + q0) * 6;
        if (t < QT * 6) {
            int qi = t / 6, d = t % 6;
            float v = pb[t];
            if (d < 3) s_pc[qi][d] = v; else s_ps[qi][d - 3] = v;
        }
    }
    __syncthreads();

    // ---- softmax: one thread per q (21 exps, trivial) ----
    if (t < QT) {
        float e[NL];
        float s = 0.0f;
        #pragma unroll
        for (int c = 0; c < NL; c++) { e[c] = expf(s_logits[t * NL + c]); s += e[c]; }
        float inv = 1.0f / s;
        #pragma unroll
        for (int c = 0; c < NC; c++) s_probs[t * NC + c] = e[c] * inv;
    }
    __syncthreads();

    // ---- main loop: each thread produces out[b, q0+qi, t] ----
    float* orow = out + (((size_t)b * QQ + q0) * NN) + t;

    #pragma unroll 4
    for (int qi = 0; qi < QT; qi++) {
        const float pcx = s_pc[qi][0], pcy = s_pc[qi][1], pcz = s_pc[qi][2];

        const float dx = pcx - tcx, dy = pcy - tcy, dz = pcz - tcz;
        const float d2 = dx * dx + dy * dy + dz * dz;

        float r;
        if (d2 > CT2) {
            // center_cost = inf -> total = inf -> INF_REPLACE exactly
            r = INF_REPLACE;
        } else {
            const float dist = sqrtf(d2);
            const float psx = s_ps[qi][0], psy = s_ps[qi][1], psz = s_ps[qi][2];

            const float min1x = pcx - 0.5f * psx, max1x = pcx + 0.5f * psx;
            const float min1y = pcy - 0.5f * psy, max1y = pcy + 0.5f * psy;
            const float min1z = pcz - 0.5f * psz, max1z = pcz + 0.5f * psz;

            float ix = fminf(max1x, max2x) - fmaxf(min1x, min2x); ix = fmaxf(ix, 0.0f);
            float iy = fminf(max1y, max2y) - fmaxf(min1y, min2y); iy = fmaxf(iy, 0.0f);
            float iz = fminf(max1z, max2z) - fmaxf(min1z, min2z); iz = fmaxf(iz, 0.0f);

            const float inter = ix * iy * iz;
            const float vol1  = psx * psy * psz;
            const float uni   = vol1 + vol2 - inter;
            const float iou   = (uni > 0.0f) ? (inter / uni) : 0.0f;

            const float cls = -s_probs[qi * NC + lbl];
            r = COST_CLASS * cls + COST_CENTER * dist + COST_IOU * (1.0f - iou);
        }
        orow[(size_t)qi * NN] = r;
    }
}

extern "C" void kernel_launch(void* const* d_in, const int* in_sizes, int n_in,
                              void* d_out, int out_size)
{
    const float* logits = (const float*)d_in[0];  // [B,Q,21]
    const float* pboxes = (const float*)d_in[1];  // [B,Q,6]
    const int*   labels = (const int*)  d_in[2];  // [B,N]
    const float* tboxes = (const float*)d_in[3];  // [B,N,6]
    float*       out    = (float*)d_out;          // [B,Q,N]

    dim3 grid(BB * (QQ / QT));
    dim3 block(256);
    matcher_kernel<<<grid, block>>>(logits, pboxes, labels, tboxes, out);
}